// round 1
// baseline (speedup 1.0000x reference)
#include <cuda_runtime.h>
#include <math.h>

#define BATCH 4
#define SEQ   1024
#define DIM   1024
#define NH    16
#define HDIM  64
#define MROWS (BATCH*SEQ)   /* 4096 */
#define NCOLS (3*DIM)       /* 3072 */
#define QK_SCALE 0.125f     /* 1/sqrt(64) */

// 50.3 MB scratch for qkv = x@W + b   (layout [4096][3072], q|k|v blocks of 1024 cols)
__device__ float g_qkv[(size_t)MROWS * NCOLS];

// ---------------------------------------------------------------------------
// QKV GEMM: C[M,3D] = X[M,D] @ W[D,3D] + bias.  128x128 tile, BK=8, 256 thr.
// ---------------------------------------------------------------------------
__global__ __launch_bounds__(256) void qkv_gemm_kernel(
    const float* __restrict__ X, const float* __restrict__ W,
    const float* __restrict__ bias)
{
    __shared__ float As[8][128];
    __shared__ float Bs[8][128];

    const int tid = threadIdx.x;
    const int m0 = blockIdx.y * 128;
    const int n0 = blockIdx.x * 128;

    // A load: thread -> (row ar, k-quad ak)
    const int ar = tid >> 1;
    const int ak = (tid & 1) * 4;
    // B load: thread -> (row br, col bc)
    const int br = tid >> 5;
    const int bc = (tid & 31) * 4;

    const int ty = tid >> 4;   // 0..15 -> 8 rows each
    const int tx = tid & 15;   // 0..15 -> 8 cols each

    const float* Xp = X + (size_t)(m0 + ar) * DIM + ak;
    const float* Wp = W + (size_t)br * NCOLS + n0 + bc;

    float acc[8][8];
    #pragma unroll
    for (int i = 0; i < 8; i++)
        #pragma unroll
        for (int j = 0; j < 8; j++) acc[i][j] = 0.f;

    for (int k0 = 0; k0 < DIM; k0 += 8) {
        float4 av = *(const float4*)(Xp + k0);
        float4 bv = *(const float4*)(Wp + (size_t)k0 * NCOLS);
        __syncthreads();
        As[ak + 0][ar] = av.x;
        As[ak + 1][ar] = av.y;
        As[ak + 2][ar] = av.z;
        As[ak + 3][ar] = av.w;
        *(float4*)&Bs[br][bc] = bv;
        __syncthreads();

        #pragma unroll
        for (int k = 0; k < 8; k++) {
            float a[8], b[8];
            #pragma unroll
            for (int i = 0; i < 8; i += 4) {
                float4 t = *(const float4*)&As[k][ty * 8 + i];
                a[i] = t.x; a[i+1] = t.y; a[i+2] = t.z; a[i+3] = t.w;
            }
            #pragma unroll
            for (int j = 0; j < 8; j += 4) {
                float4 t = *(const float4*)&Bs[k][tx * 8 + j];
                b[j] = t.x; b[j+1] = t.y; b[j+2] = t.z; b[j+3] = t.w;
            }
            #pragma unroll
            for (int i = 0; i < 8; i++)
                #pragma unroll
                for (int j = 0; j < 8; j++)
                    acc[i][j] += a[i] * b[j];
        }
    }

    // Epilogue: add bias, store
    #pragma unroll
    for (int i = 0; i < 8; i++) {
        const int m = m0 + ty * 8 + i;
        float* crow = g_qkv + (size_t)m * NCOLS + n0 + tx * 8;
        #pragma unroll
        for (int j = 0; j < 8; j += 4) {
            float4 o;
            o.x = acc[i][j+0] + bias[n0 + tx*8 + j + 0];
            o.y = acc[i][j+1] + bias[n0 + tx*8 + j + 1];
            o.z = acc[i][j+2] + bias[n0 + tx*8 + j + 2];
            o.w = acc[i][j+3] + bias[n0 + tx*8 + j + 3];
            *(float4*)(crow + j) = o;
        }
    }
}

// ---------------------------------------------------------------------------
// Flash attention: one block per (b, h, q-tile of 64). 256 threads.
// Thread (r = tid/4, j = tid%4): row r, score cols j+4i, out cols cc*16+j*4.
// P never hits smem: exchanged inside the row-quad via shfl(width=4).
// ---------------------------------------------------------------------------
#define KPAD 68   /* 64 + 4 floats: 16B-aligned pad -> conflict-free LDS.128 */

__global__ __launch_bounds__(256) void attn_kernel(
    const int* __restrict__ mask, float* __restrict__ out)
{
    __shared__ float Ks[64][KPAD];
    __shared__ float Vs[64][KPAD];

    const int qt = blockIdx.x;      // 0..15
    const int bh = blockIdx.y;      // 0..63
    const int b  = bh >> 4;
    const int h  = bh & 15;

    const int tid = threadIdx.x;
    const int r   = tid >> 2;       // 0..63
    const int j   = tid & 3;        // 0..3

    const int qrow = qt * 64 + r;
    const float* qptr = g_qkv + (size_t)(b * SEQ + qrow) * NCOLS + h * HDIM;

    // Q row in registers, pre-scaled
    float4 qv[16];
    #pragma unroll
    for (int i = 0; i < 16; i++) {
        float4 t = *(const float4*)(qptr + i * 4);
        t.x *= QK_SCALE; t.y *= QK_SCALE; t.z *= QK_SCALE; t.w *= QK_SCALE;
        qv[i] = t;
    }

    float m_run = -INFINITY;
    float l_run = 0.f;
    float4 acc[4];
    #pragma unroll
    for (int cc = 0; cc < 4; cc++) acc[cc] = make_float4(0.f, 0.f, 0.f, 0.f);

    for (int kt = 0; kt < 16; kt++) {
        __syncthreads();   // previous tile's Vs reads complete
        // Cooperative K/V tile load: 1024 float4 each, 4 per thread
        #pragma unroll
        for (int it = 0; it < 4; it++) {
            int idx = tid + 256 * it;
            int row = idx >> 4;
            int c4  = idx & 15;
            size_t base = (size_t)(b * SEQ + kt * 64 + row) * NCOLS + h * HDIM + c4 * 4;
            *(float4*)&Ks[row][c4 * 4] = *(const float4*)(g_qkv + base + DIM);
            *(float4*)&Vs[row][c4 * 4] = *(const float4*)(g_qkv + base + 2 * DIM);
        }
        __syncthreads();

        // Scores for this thread's 16 columns
        float sc[16];
        #pragma unroll
        for (int i = 0; i < 16; i++) {
            const int c = j + 4 * i;
            float4 ds = make_float4(0.f, 0.f, 0.f, 0.f);
            #pragma unroll
            for (int d4 = 0; d4 < 16; d4++) {
                float4 kvv = *(const float4*)&Ks[c][d4 * 4];
                ds.x += qv[d4].x * kvv.x;
                ds.y += qv[d4].y * kvv.y;
                ds.z += qv[d4].z * kvv.z;
                ds.w += qv[d4].w * kvv.w;
            }
            sc[i] = (ds.x + ds.y) + (ds.z + ds.w);
        }

        // Key-side mask
        const int* mrow = mask + b * SEQ + kt * 64;
        #pragma unroll
        for (int i = 0; i < 16; i++) {
            if (__ldg(&mrow[j + 4 * i]) == 0) sc[i] = -INFINITY;
        }

        // Row max across 16 local + quad (lanes j..j^3 within warp)
        float mx = sc[0];
        #pragma unroll
        for (int i = 1; i < 16; i++) mx = fmaxf(mx, sc[i]);
        mx = fmaxf(mx, __shfl_xor_sync(0xffffffffu, mx, 1));
        mx = fmaxf(mx, __shfl_xor_sync(0xffffffffu, mx, 2));

        const float m_new = fmaxf(m_run, mx);
        const float alpha = __expf(m_run - m_new);  // first iter: exp(-inf)=0

        float pe[16];
        float lsum = 0.f;
        #pragma unroll
        for (int i = 0; i < 16; i++) {
            pe[i] = __expf(sc[i] - m_new);
            lsum += pe[i];
        }
        lsum += __shfl_xor_sync(0xffffffffu, lsum, 1);
        lsum += __shfl_xor_sync(0xffffffffu, lsum, 2);

        l_run = l_run * alpha + lsum;
        m_run = m_new;
        #pragma unroll
        for (int cc = 0; cc < 4; cc++) {
            acc[cc].x *= alpha; acc[cc].y *= alpha;
            acc[cc].z *= alpha; acc[cc].w *= alpha;
        }

        // PV accumulate: broadcast p across the row-quad via shfl(width=4)
        #pragma unroll
        for (int k = 0; k < 64; k++) {
            const float p = __shfl_sync(0xffffffffu, pe[k >> 2], k & 3, 4);
            #pragma unroll
            for (int cc = 0; cc < 4; cc++) {
                float4 v = *(const float4*)&Vs[k][cc * 16 + j * 4];
                acc[cc].x += p * v.x;
                acc[cc].y += p * v.y;
                acc[cc].z += p * v.z;
                acc[cc].w += p * v.w;
            }
        }
    }

    // Epilogue: normalize and write out[b][qrow][h*64 + col]
    const float inv = 1.f / l_run;
    float* orow = out + (size_t)(b * SEQ + qrow) * DIM + h * HDIM;
    #pragma unroll
    for (int cc = 0; cc < 4; cc++) {
        float4 o;
        o.x = acc[cc].x * inv; o.y = acc[cc].y * inv;
        o.z = acc[cc].z * inv; o.w = acc[cc].w * inv;
        *(float4*)(orow + cc * 16 + j * 4) = o;
    }
}

// ---------------------------------------------------------------------------
extern "C" void kernel_launch(void* const* d_in, const int* in_sizes, int n_in,
                              void* d_out, int out_size)
{
    const float* x    = (const float*)d_in[0];   // [4,1024,1024]
    const int*   mask = (const int*)  d_in[1];   // [4,1024]
    const float* W    = (const float*)d_in[2];   // [1024,3072]
    const float* bias = (const float*)d_in[3];   // [3072]
    // d_in[4] = num_heads (compile-time 16)
    float* out = (float*)d_out;                  // [4,1024,1024]

    dim3 gg(NCOLS / 128, MROWS / 128);           // (24, 32)
    qkv_gemm_kernel<<<gg, 256>>>(x, W, bias);

    dim3 ga(SEQ / 64, BATCH * NH);               // (16, 64)
    attn_kernel<<<ga, 256>>>(mask, out);
}

// round 2
// speedup vs baseline: 1.5664x; 1.5664x over previous
#include <cuda_runtime.h>
#include <math.h>

#define BATCH 4
#define SEQ   1024
#define DIM   1024
#define NH    16
#define HDIM  64
#define MROWS (BATCH*SEQ)   /* 4096 */
#define NCOLS (3*DIM)       /* 3072 */
#define QK_SCALE 0.125f     /* 1/sqrt(64) */

typedef unsigned long long ull;

__device__ __forceinline__ ull p2(float lo, float hi) {
    ull r; asm("mov.b64 %0, {%1,%2};" : "=l"(r) : "f"(lo), "f"(hi)); return r;
}
__device__ __forceinline__ void up2(float& lo, float& hi, ull v) {
    asm("mov.b64 {%0,%1}, %2;" : "=f"(lo), "=f"(hi) : "l"(v));
}
__device__ __forceinline__ ull ffma2(ull a, ull b, ull c) {
    ull d; asm("fma.rn.f32x2 %0, %1, %2, %3;" : "=l"(d) : "l"(a), "l"(b), "l"(c)); return d;
}
__device__ __forceinline__ ull fmul2(ull a, ull b) {
    ull d; asm("mul.rn.f32x2 %0, %1, %2;" : "=l"(d) : "l"(a), "l"(b)); return d;
}

// 50.3 MB scratch: qkv = x@W + b, layout [4096][3072] (q|k|v blocks of 1024 cols)
__device__ float g_qkv[(size_t)MROWS * NCOLS];

// ---------------------------------------------------------------------------
// QKV GEMM: 128x128 tile, BK=8, 256 thr, 8x8 microtile, packed f32x2 math.
// ---------------------------------------------------------------------------
__global__ __launch_bounds__(256, 2) void qkv_gemm_kernel(
    const float* __restrict__ X, const float* __restrict__ W,
    const float* __restrict__ bias)
{
    __shared__ float As[8][128];
    __shared__ float Bs[8][128];

    const int tid = threadIdx.x;
    const int m0 = blockIdx.y * 128;
    const int n0 = blockIdx.x * 128;

    const int ar = tid >> 1;            // A: row, k-quad
    const int ak = (tid & 1) * 4;
    const int br = tid >> 5;            // B: k-row, col
    const int bc = (tid & 31) * 4;

    const int ty = tid >> 4;            // 8 rows each
    const int tx = tid & 15;            // 8 cols each

    const float* Xp = X + (size_t)(m0 + ar) * DIM + ak;
    const float* Wp = W + (size_t)br * NCOLS + n0 + bc;

    ull acc2[4][8];                      // [row-pair][col]
    #pragma unroll
    for (int i = 0; i < 4; i++)
        #pragma unroll
        for (int j = 0; j < 8; j++) acc2[i][j] = 0ull;

    for (int k0 = 0; k0 < DIM; k0 += 8) {
        float4 av = *(const float4*)(Xp + k0);
        float4 bv = *(const float4*)(Wp + (size_t)k0 * NCOLS);
        __syncthreads();
        As[ak + 0][ar] = av.x;
        As[ak + 1][ar] = av.y;
        As[ak + 2][ar] = av.z;
        As[ak + 3][ar] = av.w;
        *(float4*)&Bs[br][bc] = bv;
        __syncthreads();

        #pragma unroll
        for (int k = 0; k < 8; k++) {
            float4 t0 = *(const float4*)&As[k][ty * 8];
            float4 t1 = *(const float4*)&As[k][ty * 8 + 4];
            ull A2[4];
            A2[0] = p2(t0.x, t0.y); A2[1] = p2(t0.z, t0.w);
            A2[2] = p2(t1.x, t1.y); A2[3] = p2(t1.z, t1.w);
            float4 u0 = *(const float4*)&Bs[k][tx * 8];
            float4 u1 = *(const float4*)&Bs[k][tx * 8 + 4];
            ull Bd[8];
            Bd[0] = p2(u0.x, u0.x); Bd[1] = p2(u0.y, u0.y);
            Bd[2] = p2(u0.z, u0.z); Bd[3] = p2(u0.w, u0.w);
            Bd[4] = p2(u1.x, u1.x); Bd[5] = p2(u1.y, u1.y);
            Bd[6] = p2(u1.z, u1.z); Bd[7] = p2(u1.w, u1.w);
            #pragma unroll
            for (int ip = 0; ip < 4; ip++)
                #pragma unroll
                for (int j = 0; j < 8; j++)
                    acc2[ip][j] = ffma2(A2[ip], Bd[j], acc2[ip][j]);
        }
    }

    // Epilogue: unpack pairs, add bias, store
    #pragma unroll
    for (int ip = 0; ip < 4; ip++) {
        float c0[8], c1[8];
        #pragma unroll
        for (int j = 0; j < 8; j++) up2(c0[j], c1[j], acc2[ip][j]);
        #pragma unroll
        for (int l = 0; l < 2; l++) {
            const float* cr = l ? c1 : c0;
            const int m = m0 + ty * 8 + ip * 2 + l;
            float* crow = g_qkv + (size_t)m * NCOLS + n0 + tx * 8;
            #pragma unroll
            for (int j = 0; j < 8; j += 4) {
                float4 o;
                o.x = cr[j+0] + bias[n0 + tx*8 + j + 0];
                o.y = cr[j+1] + bias[n0 + tx*8 + j + 1];
                o.z = cr[j+2] + bias[n0 + tx*8 + j + 2];
                o.w = cr[j+3] + bias[n0 + tx*8 + j + 3];
                *(float4*)(crow + j) = o;
            }
        }
    }
}

// ---------------------------------------------------------------------------
// Flash attention as two register-blocked GEMMs.
// Block: q-tile 128 x k-tile 64, 256 threads (16x16), 8(q)x4(k) microtiles.
// Q,K stored d-major in smem; P materialized in smem for PV.
// ---------------------------------------------------------------------------
#define QTL  128
#define KTL  64
#define QPAD 132   /* 128+4: rows 16B aligned */
#define KPD  68    /* 64+4 */

#define ATTN_SMEM ((64*QPAD + 64*KPD + 64*KPD + 64*QPAD) * 4)

__global__ __launch_bounds__(256, 2) void attn_kernel(
    const int* __restrict__ mask, float* __restrict__ out)
{
    extern __shared__ float sm[];
    float* Qs = sm;                      // [64 d][QPAD]
    float* Ks = Qs + 64 * QPAD;          // [64 d][KPD]
    float* Vs = Ks + 64 * KPD;           // [64 k][KPD]
    float* Ps = Vs + 64 * KPD;           // [64 k][QPAD]

    const int q0 = blockIdx.x * QTL;
    const int bh = blockIdx.y;
    const int b  = bh >> 4;
    const int h  = bh & 15;

    const int tid = threadIdx.x;
    const int tx  = tid & 15;            // k-cols / d-cols: tx*4..+3
    const int ty  = tid >> 4;            // q-rows: ty*8..+7

    // ---- Load Q tile (transposed to d-major), pre-scaled ----
    #pragma unroll
    for (int it = 0; it < 8; it++) {
        int idx = tid + 256 * it;
        int qr  = idx >> 4;
        int d4  = (idx & 15) * 4;
        float4 t = *(const float4*)(g_qkv + (size_t)(b * SEQ + q0 + qr) * NCOLS + h * HDIM + d4);
        Qs[(d4 + 0) * QPAD + qr] = t.x * QK_SCALE;
        Qs[(d4 + 1) * QPAD + qr] = t.y * QK_SCALE;
        Qs[(d4 + 2) * QPAD + qr] = t.z * QK_SCALE;
        Qs[(d4 + 3) * QPAD + qr] = t.w * QK_SCALE;
    }

    float m_run[8], l_run[8];
    #pragma unroll
    for (int i = 0; i < 8; i++) { m_run[i] = -INFINITY; l_run[i] = 0.f; }
    ull accO2[4][4];                     // [q-pair][d-col]
    #pragma unroll
    for (int i = 0; i < 4; i++)
        #pragma unroll
        for (int j = 0; j < 4; j++) accO2[i][j] = 0ull;

    for (int kt = 0; kt < 16; kt++) {
        __syncthreads();
        // ---- Load K (transposed, d-major) and V (natural) ----
        #pragma unroll
        for (int it = 0; it < 4; it++) {
            int idx = tid + 256 * it;
            int kr  = idx >> 4;
            int d4  = (idx & 15) * 4;
            size_t base = (size_t)(b * SEQ + kt * KTL + kr) * NCOLS + h * HDIM + d4;
            float4 kv = *(const float4*)(g_qkv + base + DIM);
            float4 vv = *(const float4*)(g_qkv + base + 2 * DIM);
            Ks[(d4 + 0) * KPD + kr] = kv.x;
            Ks[(d4 + 1) * KPD + kr] = kv.y;
            Ks[(d4 + 2) * KPD + kr] = kv.z;
            Ks[(d4 + 3) * KPD + kr] = kv.w;
            *(float4*)&Vs[kr * KPD + d4] = vv;
        }
        __syncthreads();

        // ---- S = Q @ K^T  (8x4 microtile, f32x2 pairs along q) ----
        ull acc2[4][4];
        #pragma unroll
        for (int i = 0; i < 4; i++)
            #pragma unroll
            for (int j = 0; j < 4; j++) acc2[i][j] = 0ull;

        #pragma unroll 4
        for (int d = 0; d < 64; d++) {
            const float* qr = Qs + d * QPAD + ty * 8;
            float4 a0 = *(const float4*)qr;
            float4 a1 = *(const float4*)(qr + 4);
            ull A2[4];
            A2[0] = p2(a0.x, a0.y); A2[1] = p2(a0.z, a0.w);
            A2[2] = p2(a1.x, a1.y); A2[3] = p2(a1.z, a1.w);
            float4 bv = *(const float4*)(Ks + d * KPD + tx * 4);
            ull Bd[4];
            Bd[0] = p2(bv.x, bv.x); Bd[1] = p2(bv.y, bv.y);
            Bd[2] = p2(bv.z, bv.z); Bd[3] = p2(bv.w, bv.w);
            #pragma unroll
            for (int qp = 0; qp < 4; qp++)
                #pragma unroll
                for (int kc = 0; kc < 4; kc++)
                    acc2[qp][kc] = ffma2(A2[qp], Bd[kc], acc2[qp][kc]);
        }

        float s[8][4];
        #pragma unroll
        for (int qp = 0; qp < 4; qp++)
            #pragma unroll
            for (int kc = 0; kc < 4; kc++)
                up2(s[2*qp][kc], s[2*qp+1][kc], acc2[qp][kc]);

        // ---- key-side mask ----
        int4 mv = *(const int4*)(mask + b * SEQ + kt * KTL + tx * 4);
        #pragma unroll
        for (int qi = 0; qi < 8; qi++) {
            if (mv.x == 0) s[qi][0] = -INFINITY;
            if (mv.y == 0) s[qi][1] = -INFINITY;
            if (mv.z == 0) s[qi][2] = -INFINITY;
            if (mv.w == 0) s[qi][3] = -INFINITY;
        }

        // ---- online softmax (row spans 16 tx lanes, shuffle width 16) ----
        float alpha[8];
        #pragma unroll
        for (int qi = 0; qi < 8; qi++) {
            float mx = fmaxf(fmaxf(s[qi][0], s[qi][1]), fmaxf(s[qi][2], s[qi][3]));
            mx = fmaxf(mx, __shfl_xor_sync(0xffffffffu, mx, 1, 16));
            mx = fmaxf(mx, __shfl_xor_sync(0xffffffffu, mx, 2, 16));
            mx = fmaxf(mx, __shfl_xor_sync(0xffffffffu, mx, 4, 16));
            mx = fmaxf(mx, __shfl_xor_sync(0xffffffffu, mx, 8, 16));
            float m_new = fmaxf(m_run[qi], mx);
            alpha[qi] = __expf(m_run[qi] - m_new);
            m_run[qi] = m_new;
            float lsum = 0.f;
            #pragma unroll
            for (int kc = 0; kc < 4; kc++) {
                s[qi][kc] = __expf(s[qi][kc] - m_new);   // reuse s as p
                lsum += s[qi][kc];
            }
            lsum += __shfl_xor_sync(0xffffffffu, lsum, 1, 16);
            lsum += __shfl_xor_sync(0xffffffffu, lsum, 2, 16);
            lsum += __shfl_xor_sync(0xffffffffu, lsum, 4, 16);
            lsum += __shfl_xor_sync(0xffffffffu, lsum, 8, 16);
            l_run[qi] = l_run[qi] * alpha[qi] + lsum;
        }

        // ---- rescale O accumulators (packed alpha pairs) ----
        #pragma unroll
        for (int qp = 0; qp < 4; qp++) {
            ull ad = p2(alpha[2*qp], alpha[2*qp+1]);
            #pragma unroll
            for (int dc = 0; dc < 4; dc++)
                accO2[qp][dc] = fmul2(accO2[qp][dc], ad);
        }

        // ---- write P to smem (k-major, q minor) ----
        #pragma unroll
        for (int kc = 0; kc < 4; kc++) {
            float* prow = Ps + (tx * 4 + kc) * QPAD + ty * 8;
            float4 w0 = make_float4(s[0][kc], s[1][kc], s[2][kc], s[3][kc]);
            float4 w1 = make_float4(s[4][kc], s[5][kc], s[6][kc], s[7][kc]);
            *(float4*)prow = w0;
            *(float4*)(prow + 4) = w1;
        }
        __syncthreads();

        // ---- O += P @ V  (8x4 microtile, f32x2 pairs along q) ----
        #pragma unroll 4
        for (int k = 0; k < 64; k++) {
            const float* pr = Ps + k * QPAD + ty * 8;
            float4 a0 = *(const float4*)pr;
            float4 a1 = *(const float4*)(pr + 4);
            ull A2[4];
            A2[0] = p2(a0.x, a0.y); A2[1] = p2(a0.z, a0.w);
            A2[2] = p2(a1.x, a1.y); A2[3] = p2(a1.z, a1.w);
            float4 vv = *(const float4*)(Vs + k * KPD + tx * 4);
            ull Bd[4];
            Bd[0] = p2(vv.x, vv.x); Bd[1] = p2(vv.y, vv.y);
            Bd[2] = p2(vv.z, vv.z); Bd[3] = p2(vv.w, vv.w);
            #pragma unroll
            for (int qp = 0; qp < 4; qp++)
                #pragma unroll
                for (int dc = 0; dc < 4; dc++)
                    accO2[qp][dc] = ffma2(A2[qp], Bd[dc], accO2[qp][dc]);
        }
    }

    // ---- epilogue: normalize, store ----
    #pragma unroll
    for (int qp = 0; qp < 4; qp++) {
        float o0[4], o1[4];
        #pragma unroll
        for (int dc = 0; dc < 4; dc++) up2(o0[dc], o1[dc], accO2[qp][dc]);
        #pragma unroll
        for (int l = 0; l < 2; l++) {
            const int qi = qp * 2 + l;
            const float inv = 1.f / l_run[qi];
            const float* oc = l ? o1 : o0;
            float4 o;
            o.x = oc[0] * inv; o.y = oc[1] * inv;
            o.z = oc[2] * inv; o.w = oc[3] * inv;
            *(float4*)(out + (size_t)(b * SEQ + q0 + ty * 8 + qi) * DIM + h * HDIM + tx * 4) = o;
        }
    }
}

// ---------------------------------------------------------------------------
extern "C" void kernel_launch(void* const* d_in, const int* in_sizes, int n_in,
                              void* d_out, int out_size)
{
    const float* x    = (const float*)d_in[0];   // [4,1024,1024]
    const int*   mask = (const int*)  d_in[1];   // [4,1024]
    const float* W    = (const float*)d_in[2];   // [1024,3072]
    const float* bias = (const float*)d_in[3];   // [3072]
    float* out = (float*)d_out;                  // [4,1024,1024]

    cudaFuncSetAttribute(attn_kernel,
                         cudaFuncAttributeMaxDynamicSharedMemorySize, ATTN_SMEM);

    dim3 gg(NCOLS / 128, MROWS / 128);           // (24, 32)
    qkv_gemm_kernel<<<gg, 256>>>(x, W, bias);

    dim3 ga(SEQ / QTL, BATCH * NH);              // (8, 64)
    attn_kernel<<<ga, 256, ATTN_SMEM>>>(mask, out);
}

// round 8
// speedup vs baseline: 2.4505x; 1.5644x over previous
#include <cuda_runtime.h>
#include <cuda_bf16.h>
#include <math.h>

#define BATCH 4
#define SEQ   1024
#define DIM   1024
#define NH    16
#define HDIM  64
#define MROWS (BATCH*SEQ)   /* 4096 */
#define NCOLS (3*DIM)       /* 3072 */
#define QK_SCALE 0.125f     /* 1/sqrt(64) */

typedef unsigned long long ull;

// ---------------- f32x2 helpers (attention kernel) ----------------
__device__ __forceinline__ ull p2(float lo, float hi) {
    ull r; asm("mov.b64 %0, {%1,%2};" : "=l"(r) : "f"(lo), "f"(hi)); return r;
}
__device__ __forceinline__ void up2(float& lo, float& hi, ull v) {
    asm("mov.b64 {%0,%1}, %2;" : "=f"(lo), "=f"(hi) : "l"(v));
}
__device__ __forceinline__ ull ffma2(ull a, ull b, ull c) {
    ull d; asm("fma.rn.f32x2 %0, %1, %2, %3;" : "=l"(d) : "l"(a), "l"(b), "l"(c)); return d;
}
__device__ __forceinline__ ull fmul2(ull a, ull b) {
    ull d; asm("mul.rn.f32x2 %0, %1, %2;" : "=l"(d) : "l"(a), "l"(b)); return d;
}

// ---------------- warp-MMA helpers (baseline sm_80 features only) ----------------
__device__ __forceinline__ unsigned smem_u32(const void* p) {
    unsigned a;
    asm("{ .reg .u64 t; cvta.to.shared.u64 t, %1; cvt.u32.u64 %0, t; }" : "=r"(a) : "l"(p));
    return a;
}
__device__ __forceinline__ void ldm_x4(unsigned* r, unsigned addr) {
    asm volatile("ldmatrix.sync.aligned.m8n8.x4.shared.b16 {%0,%1,%2,%3}, [%4];"
        : "=r"(r[0]), "=r"(r[1]), "=r"(r[2]), "=r"(r[3]) : "r"(addr));
}
__device__ __forceinline__ void mma16816(float* c, const unsigned* a, unsigned b0, unsigned b1) {
    asm volatile("mma.sync.aligned.m16n8k16.row.col.f32.bf16.bf16.f32 "
        "{%0,%1,%2,%3}, {%4,%5,%6,%7}, {%8,%9}, {%0,%1,%2,%3};"
        : "+f"(c[0]), "+f"(c[1]), "+f"(c[2]), "+f"(c[3])
        : "r"(a[0]), "r"(a[1]), "r"(a[2]), "r"(a[3]), "r"(b0), "r"(b1));
}
__device__ __forceinline__ void cp16(unsigned dst, const void* src) {
    asm volatile("cp.async.cg.shared.global [%0], [%1], 16;" :: "r"(dst), "l"(src));
}
#define CP_COMMIT() asm volatile("cp.async.commit_group;" ::: "memory")
#define CP_WAIT(n)  asm volatile("cp.async.wait_group %0;" :: "n"(n) : "memory")

// ---------------- global scratch ----------------
__device__ float g_qkv[(size_t)MROWS * NCOLS];                  // 50.3 MB
__device__ unsigned short g_xh[(size_t)MROWS * DIM];            // X hi bf16
__device__ unsigned short g_xl[(size_t)MROWS * DIM];            // X lo bf16
__device__ unsigned short g_wth[(size_t)NCOLS * DIM];           // W^T hi  [N=3072][K=1024]
__device__ unsigned short g_wtl[(size_t)NCOLS * DIM];           // W^T lo

// ---------------------------------------------------------------------------
// Convert X -> hi/lo bf16 (row-major [4096][1024])
// ---------------------------------------------------------------------------
__global__ __launch_bounds__(256) void xconv_kernel(const float* __restrict__ X)
{
    size_t i = ((size_t)blockIdx.x * 256 + threadIdx.x) * 4;
    float4 v = *(const float4*)(X + i);
    float f[4] = {v.x, v.y, v.z, v.w};
    unsigned short h[4], l[4];
    #pragma unroll
    for (int j = 0; j < 4; j++) {
        __nv_bfloat16 hb = __float2bfloat16_rn(f[j]);
        h[j] = __bfloat16_as_ushort(hb);
        l[j] = __bfloat16_as_ushort(__float2bfloat16_rn(f[j] - __bfloat162float(hb)));
    }
    uint2 hv = make_uint2((unsigned)h[0] | ((unsigned)h[1] << 16),
                          (unsigned)h[2] | ((unsigned)h[3] << 16));
    uint2 lv = make_uint2((unsigned)l[0] | ((unsigned)l[1] << 16),
                          (unsigned)l[2] | ((unsigned)l[3] << 16));
    *(uint2*)(g_xh + i) = hv;
    *(uint2*)(g_xl + i) = lv;
}

// ---------------------------------------------------------------------------
// Transpose + convert W [1024][3072] -> W^T hi/lo bf16 [3072][1024]
// ---------------------------------------------------------------------------
__global__ __launch_bounds__(256) void wconv_kernel(const float* __restrict__ W)
{
    __shared__ float t[32][33];
    const int n0 = blockIdx.x * 32;
    const int k0 = blockIdx.y * 32;
    const int tx = threadIdx.x & 31;
    const int ty = threadIdx.x >> 5;   // 0..7
    #pragma unroll
    for (int i = 0; i < 4; i++)
        t[ty + 8 * i][tx] = W[(size_t)(k0 + ty + 8 * i) * NCOLS + n0 + tx];
    __syncthreads();
    #pragma unroll
    for (int i = 0; i < 4; i++) {
        float v = t[tx][ty + 8 * i];
        __nv_bfloat16 hb = __float2bfloat16_rn(v);
        unsigned short l = __bfloat16_as_ushort(__float2bfloat16_rn(v - __bfloat162float(hb)));
        size_t o = (size_t)(n0 + ty + 8 * i) * DIM + k0 + tx;
        g_wth[o] = __bfloat16_as_ushort(hb);
        g_wtl[o] = l;
    }
}

// ---------------------------------------------------------------------------
// QKV GEMM via warp-level HMMA (mma.sync m16n8k16 bf16, 3-term split).
// CTA 128x128, BK=32, 8 warps (2M x 4N), warp tile 64x32 (4x4 mma tiles).
// cp.async double-buffered; pad-80B smem rows -> conflict-free ldmatrix.
// ---------------------------------------------------------------------------
#define ROWB   80                        /* 32 bf16 = 64 B, padded to 80 B */
#define TILE_B (128 * ROWB)              /* 10240 B per hi/lo tile */
#define STG_B  (4 * TILE_B)              /* Ah Al Bh Bl = 40960 B per stage */
#define GEMM_SMEM (2 * STG_B)            /* 81920 B */

__global__ __launch_bounds__(256) void qkv_mma_kernel(const float* __restrict__ bias)
{
    extern __shared__ __align__(128) char smem[];
    const unsigned sb = smem_u32(smem);
    const int tid  = threadIdx.x;
    const int wid  = tid >> 5;
    const int lane = tid & 31;

    const int m0 = blockIdx.y * 128;
    const int n0 = blockIdx.x * 128;
    const int wm = (wid & 1) * 64;      // warp M offset in tile
    const int wn = (wid >> 1) * 32;     // warp N offset in tile

    float acc[4][4][4];
    #pragma unroll
    for (int i = 0; i < 4; i++)
        #pragma unroll
        for (int j = 0; j < 4; j++)
            #pragma unroll
            for (int r = 0; r < 4; r++) acc[i][j][r] = 0.f;

    // ---- stage loader: 4 tiles (Ah Al Bh Bl), 128 rows x 32 bf16 each ----
    auto load_stage = [&](int c, int buf) {
        const unsigned base = sb + buf * STG_B;
        const int k0 = c * 32;
        const unsigned short* srcs[4] = {
            g_xh  + (size_t)m0 * DIM + k0,
            g_xl  + (size_t)m0 * DIM + k0,
            g_wth + (size_t)n0 * DIM + k0,
            g_wtl + (size_t)n0 * DIM + k0 };
        #pragma unroll
        for (int t = 0; t < 4; t++) {
            #pragma unroll
            for (int it = 0; it < 2; it++) {
                int idx = tid + 256 * it;         // 0..511
                int row = idx >> 2;               // 0..127
                int c8  = idx & 3;                // 16B chunk
                cp16(base + t * TILE_B + row * ROWB + c8 * 16,
                     srcs[t] + (size_t)row * DIM + c8 * 8);
            }
        }
    };

    load_stage(0, 0);
    CP_COMMIT();

    for (int c = 0; c < 32; c++) {
        const int buf = c & 1;
        if (c + 1 < 32) {
            load_stage(c + 1, buf ^ 1);
            CP_COMMIT();
            CP_WAIT(1);
        } else {
            CP_WAIT(0);
        }
        __syncthreads();

        const unsigned sAh = sb + buf * STG_B;
        const unsigned sAl = sAh + TILE_B;
        const unsigned sBh = sAh + 2 * TILE_B;
        const unsigned sBl = sAh + 3 * TILE_B;

        #pragma unroll
        for (int k16 = 0; k16 < 2; k16++) {
            const unsigned a_off = (wm + (lane & 15)) * ROWB + (k16 * 16 + (lane >> 4) * 8) * 2;
            unsigned ah[4][4], al[4][4];
            #pragma unroll
            for (int mt = 0; mt < 4; mt++) {
                ldm_x4(ah[mt], sAh + a_off + mt * 16 * ROWB);
                ldm_x4(al[mt], sAl + a_off + mt * 16 * ROWB);
            }
            const int bmat = lane >> 3;                       // matrix id 0..3
            const unsigned b_off = (wn + (bmat >> 1) * 8 + (lane & 7)) * ROWB
                                 + (k16 * 16 + (bmat & 1) * 8) * 2;
            unsigned bh[2][4], bl[2][4];
            #pragma unroll
            for (int nt2 = 0; nt2 < 2; nt2++) {
                ldm_x4(bh[nt2], sBh + b_off + nt2 * 16 * ROWB);
                ldm_x4(bl[nt2], sBl + b_off + nt2 * 16 * ROWB);
            }
            #pragma unroll
            for (int mt = 0; mt < 4; mt++) {
                #pragma unroll
                for (int nt = 0; nt < 4; nt++) {
                    const int n2 = nt >> 1, hb = (nt & 1) * 2;
                    mma16816(acc[mt][nt], ah[mt], bh[n2][hb], bh[n2][hb + 1]);
                    mma16816(acc[mt][nt], ah[mt], bl[n2][hb], bl[n2][hb + 1]);
                    mma16816(acc[mt][nt], al[mt], bh[n2][hb], bh[n2][hb + 1]);
                }
            }
        }
        __syncthreads();
    }

    // ---- epilogue: bias + store fp32 ----
    #pragma unroll
    for (int mt = 0; mt < 4; mt++) {
        const int row = m0 + wm + mt * 16 + (lane >> 2);
        #pragma unroll
        for (int nt = 0; nt < 4; nt++) {
            const int col = n0 + wn + nt * 8 + (lane & 3) * 2;
            const float b0 = bias[col], b1 = bias[col + 1];
            float2 lo = make_float2(acc[mt][nt][0] + b0, acc[mt][nt][1] + b1);
            float2 hi = make_float2(acc[mt][nt][2] + b0, acc[mt][nt][3] + b1);
            *(float2*)(g_qkv + (size_t)row * NCOLS + col) = lo;
            *(float2*)(g_qkv + (size_t)(row + 8) * NCOLS + col) = hi;
        }
    }
}

// ---------------------------------------------------------------------------
// Flash attention (unchanged, known-good 447us version)
// ---------------------------------------------------------------------------
#define QTL  128
#define KTL  64
#define QPAD 132
#define KPD  68
#define ATTN_SMEM ((64*QPAD + 64*KPD + 64*KPD + 64*QPAD) * 4)

__global__ __launch_bounds__(256, 2) void attn_kernel(
    const int* __restrict__ mask, float* __restrict__ out)
{
    extern __shared__ float sm[];
    float* Qs = sm;
    float* Ks = Qs + 64 * QPAD;
    float* Vs = Ks + 64 * KPD;
    float* Ps = Vs + 64 * KPD;

    const int q0 = blockIdx.x * QTL;
    const int bh = blockIdx.y;
    const int b  = bh >> 4;
    const int h  = bh & 15;

    const int tid = threadIdx.x;
    const int tx  = tid & 15;
    const int ty  = tid >> 4;

    #pragma unroll
    for (int it = 0; it < 8; it++) {
        int idx = tid + 256 * it;
        int qr  = idx >> 4;
        int d4  = (idx & 15) * 4;
        float4 t = *(const float4*)(g_qkv + (size_t)(b * SEQ + q0 + qr) * NCOLS + h * HDIM + d4);
        Qs[(d4 + 0) * QPAD + qr] = t.x * QK_SCALE;
        Qs[(d4 + 1) * QPAD + qr] = t.y * QK_SCALE;
        Qs[(d4 + 2) * QPAD + qr] = t.z * QK_SCALE;
        Qs[(d4 + 3) * QPAD + qr] = t.w * QK_SCALE;
    }

    float m_run[8], l_run[8];
    #pragma unroll
    for (int i = 0; i < 8; i++) { m_run[i] = -INFINITY; l_run[i] = 0.f; }
    ull accO2[4][4];
    #pragma unroll
    for (int i = 0; i < 4; i++)
        #pragma unroll
        for (int j = 0; j < 4; j++) accO2[i][j] = 0ull;

    for (int kt = 0; kt < 16; kt++) {
        __syncthreads();
        #pragma unroll
        for (int it = 0; it < 4; it++) {
            int idx = tid + 256 * it;
            int kr  = idx >> 4;
            int d4  = (idx & 15) * 4;
            size_t base = (size_t)(b * SEQ + kt * KTL + kr) * NCOLS + h * HDIM + d4;
            float4 kv = *(const float4*)(g_qkv + base + DIM);
            float4 vv = *(const float4*)(g_qkv + base + 2 * DIM);
            Ks[(d4 + 0) * KPD + kr] = kv.x;
            Ks[(d4 + 1) * KPD + kr] = kv.y;
            Ks[(d4 + 2) * KPD + kr] = kv.z;
            Ks[(d4 + 3) * KPD + kr] = kv.w;
            *(float4*)&Vs[kr * KPD + d4] = vv;
        }
        __syncthreads();

        ull acc2[4][4];
        #pragma unroll
        for (int i = 0; i < 4; i++)
            #pragma unroll
            for (int j = 0; j < 4; j++) acc2[i][j] = 0ull;

        #pragma unroll 4
        for (int d = 0; d < 64; d++) {
            const float* qr = Qs + d * QPAD + ty * 8;
            float4 a0 = *(const float4*)qr;
            float4 a1 = *(const float4*)(qr + 4);
            ull A2[4];
            A2[0] = p2(a0.x, a0.y); A2[1] = p2(a0.z, a0.w);
            A2[2] = p2(a1.x, a1.y); A2[3] = p2(a1.z, a1.w);
            float4 bv = *(const float4*)(Ks + d * KPD + tx * 4);
            ull Bd[4];
            Bd[0] = p2(bv.x, bv.x); Bd[1] = p2(bv.y, bv.y);
            Bd[2] = p2(bv.z, bv.z); Bd[3] = p2(bv.w, bv.w);
            #pragma unroll
            for (int qp = 0; qp < 4; qp++)
                #pragma unroll
                for (int kc = 0; kc < 4; kc++)
                    acc2[qp][kc] = ffma2(A2[qp], Bd[kc], acc2[qp][kc]);
        }

        float s[8][4];
        #pragma unroll
        for (int qp = 0; qp < 4; qp++)
            #pragma unroll
            for (int kc = 0; kc < 4; kc++)
                up2(s[2*qp][kc], s[2*qp+1][kc], acc2[qp][kc]);

        int4 mv = *(const int4*)(mask + b * SEQ + kt * KTL + tx * 4);
        #pragma unroll
        for (int qi = 0; qi < 8; qi++) {
            if (mv.x == 0) s[qi][0] = -INFINITY;
            if (mv.y == 0) s[qi][1] = -INFINITY;
            if (mv.z == 0) s[qi][2] = -INFINITY;
            if (mv.w == 0) s[qi][3] = -INFINITY;
        }

        float alpha[8];
        #pragma unroll
        for (int qi = 0; qi < 8; qi++) {
            float mx = fmaxf(fmaxf(s[qi][0], s[qi][1]), fmaxf(s[qi][2], s[qi][3]));
            mx = fmaxf(mx, __shfl_xor_sync(0xffffffffu, mx, 1, 16));
            mx = fmaxf(mx, __shfl_xor_sync(0xffffffffu, mx, 2, 16));
            mx = fmaxf(mx, __shfl_xor_sync(0xffffffffu, mx, 4, 16));
            mx = fmaxf(mx, __shfl_xor_sync(0xffffffffu, mx, 8, 16));
            float m_new = fmaxf(m_run[qi], mx);
            alpha[qi] = __expf(m_run[qi] - m_new);
            m_run[qi] = m_new;
            float lsum = 0.f;
            #pragma unroll
            for (int kc = 0; kc < 4; kc++) {
                s[qi][kc] = __expf(s[qi][kc] - m_new);
                lsum += s[qi][kc];
            }
            lsum += __shfl_xor_sync(0xffffffffu, lsum, 1, 16);
            lsum += __shfl_xor_sync(0xffffffffu, lsum, 2, 16);
            lsum += __shfl_xor_sync(0xffffffffu, lsum, 4, 16);
            lsum += __shfl_xor_sync(0xffffffffu, lsum, 8, 16);
            l_run[qi] = l_run[qi] * alpha[qi] + lsum;
        }

        #pragma unroll
        for (int qp = 0; qp < 4; qp++) {
            ull ad = p2(alpha[2*qp], alpha[2*qp+1]);
            #pragma unroll
            for (int dc = 0; dc < 4; dc++)
                accO2[qp][dc] = fmul2(accO2[qp][dc], ad);
        }

        #pragma unroll
        for (int kc = 0; kc < 4; kc++) {
            float* prow = Ps + (tx * 4 + kc) * QPAD + ty * 8;
            *(float4*)prow       = make_float4(s[0][kc], s[1][kc], s[2][kc], s[3][kc]);
            *(float4*)(prow + 4) = make_float4(s[4][kc], s[5][kc], s[6][kc], s[7][kc]);
        }
        __syncthreads();

        #pragma unroll 4
        for (int k = 0; k < 64; k++) {
            const float* pr = Ps + k * QPAD + ty * 8;
            float4 a0 = *(const float4*)pr;
            float4 a1 = *(const float4*)(pr + 4);
            ull A2[4];
            A2[0] = p2(a0.x, a0.y); A2[1] = p2(a0.z, a0.w);
            A2[2] = p2(a1.x, a1.y); A2[3] = p2(a1.z, a1.w);
            float4 vv = *(const float4*)(Vs + k * KPD + tx * 4);
            ull Bd[4];
            Bd[0] = p2(vv.x, vv.x); Bd[1] = p2(vv.y, vv.y);
            Bd[2] = p2(vv.z, vv.z); Bd[3] = p2(vv.w, vv.w);
            #pragma unroll
            for (int qp = 0; qp < 4; qp++)
                #pragma unroll
                for (int dc = 0; dc < 4; dc++)
                    accO2[qp][dc] = ffma2(A2[qp], Bd[dc], accO2[qp][dc]);
        }
    }

    #pragma unroll
    for (int qp = 0; qp < 4; qp++) {
        float o0[4], o1[4];
        #pragma unroll
        for (int dc = 0; dc < 4; dc++) up2(o0[dc], o1[dc], accO2[qp][dc]);
        #pragma unroll
        for (int l = 0; l < 2; l++) {
            const int qi = qp * 2 + l;
            const float inv = 1.f / l_run[qi];
            const float* oc = l ? o1 : o0;
            float4 o;
            o.x = oc[0] * inv; o.y = oc[1] * inv;
            o.z = oc[2] * inv; o.w = oc[3] * inv;
            *(float4*)(out + (size_t)(b * SEQ + q0 + ty * 8 + qi) * DIM + h * HDIM + tx * 4) = o;
        }
    }
}

// ---------------------------------------------------------------------------
extern "C" void kernel_launch(void* const* d_in, const int* in_sizes, int n_in,
                              void* d_out, int out_size)
{
    const float* x    = (const float*)d_in[0];   // [4,1024,1024]
    const int*   mask = (const int*)  d_in[1];   // [4,1024]
    const float* W    = (const float*)d_in[2];   // [1024,3072]
    const float* bias = (const float*)d_in[3];   // [3072]
    float* out = (float*)d_out;                  // [4,1024,1024]

    cudaFuncSetAttribute(qkv_mma_kernel,
                         cudaFuncAttributeMaxDynamicSharedMemorySize, GEMM_SMEM);
    cudaFuncSetAttribute(attn_kernel,
                         cudaFuncAttributeMaxDynamicSharedMemorySize, ATTN_SMEM);

    xconv_kernel<<<(MROWS * DIM) / (256 * 4), 256>>>(x);
    wconv_kernel<<<dim3(NCOLS / 32, DIM / 32), 256>>>(W);

    dim3 gg(NCOLS / 128, MROWS / 128);           // (24, 32)
    qkv_mma_kernel<<<gg, 256, GEMM_SMEM>>>(bias);

    dim3 ga(SEQ / QTL, BATCH * NH);              // (8, 64)
    attn_kernel<<<ga, 256, ATTN_SMEM>>>(mask, out);
}

// round 10
// speedup vs baseline: 3.7228x; 1.5192x over previous
#include <cuda_runtime.h>
#include <cuda_bf16.h>
#include <math.h>

#define BATCH 4
#define SEQ   1024
#define DIM   1024
#define NH    16
#define HDIM  64
#define MROWS (BATCH*SEQ)   /* 4096 */
#define NCOLS (3*DIM)       /* 3072 */
#define QK_SCALE 0.125f     /* 1/sqrt(64) */

typedef unsigned long long ull;

// ---------------- warp-MMA helpers (baseline sm_80 features only) ----------------
__device__ __forceinline__ unsigned smem_u32(const void* p) {
    unsigned a;
    asm("{ .reg .u64 t; cvta.to.shared.u64 t, %1; cvt.u32.u64 %0, t; }" : "=r"(a) : "l"(p));
    return a;
}
__device__ __forceinline__ void ldm_x4(unsigned* r, unsigned addr) {
    asm volatile("ldmatrix.sync.aligned.m8n8.x4.shared.b16 {%0,%1,%2,%3}, [%4];"
        : "=r"(r[0]), "=r"(r[1]), "=r"(r[2]), "=r"(r[3]) : "r"(addr));
}
__device__ __forceinline__ void ldm_x4t(unsigned* r, unsigned addr) {
    asm volatile("ldmatrix.sync.aligned.m8n8.x4.trans.shared.b16 {%0,%1,%2,%3}, [%4];"
        : "=r"(r[0]), "=r"(r[1]), "=r"(r[2]), "=r"(r[3]) : "r"(addr));
}
__device__ __forceinline__ void mma16816(float* c, const unsigned* a, unsigned b0, unsigned b1) {
    asm volatile("mma.sync.aligned.m16n8k16.row.col.f32.bf16.bf16.f32 "
        "{%0,%1,%2,%3}, {%4,%5,%6,%7}, {%8,%9}, {%0,%1,%2,%3};"
        : "+f"(c[0]), "+f"(c[1]), "+f"(c[2]), "+f"(c[3])
        : "r"(a[0]), "r"(a[1]), "r"(a[2]), "r"(a[3]), "r"(b0), "r"(b1));
}
__device__ __forceinline__ void cp16(unsigned dst, const void* src) {
    asm volatile("cp.async.cg.shared.global [%0], [%1], 16;" :: "r"(dst), "l"(src));
}
#define CP_COMMIT() asm volatile("cp.async.commit_group;" ::: "memory")
#define CP_WAIT(n)  asm volatile("cp.async.wait_group %0;" :: "n"(n) : "memory")

// pack two f32 -> bf16x2 (hi -> upper half, lo -> lower half)
__device__ __forceinline__ unsigned bfpack(float hi, float lo) {
    unsigned r; asm("cvt.rn.bf16x2.f32 %0, %1, %2;" : "=r"(r) : "f"(hi), "f"(lo)); return r;
}

// ---------------- global scratch ----------------
__device__ unsigned short g_xh[(size_t)MROWS * DIM];     // X hi bf16
__device__ unsigned short g_xl[(size_t)MROWS * DIM];     // X lo bf16
__device__ unsigned short g_wth[(size_t)NCOLS * DIM];    // W^T hi [N][K]
__device__ unsigned short g_wtl[(size_t)NCOLS * DIM];    // W^T lo
// per-head layout [(b*16+h)*1024 + s][d], bf16 hi/lo. Q pre-scaled.
__device__ unsigned short g_qh[(size_t)MROWS * DIM];
__device__ unsigned short g_ql[(size_t)MROWS * DIM];
__device__ unsigned short g_kh[(size_t)MROWS * DIM];
__device__ unsigned short g_kl[(size_t)MROWS * DIM];
__device__ unsigned short g_vh[(size_t)MROWS * DIM];
__device__ unsigned short g_vl[(size_t)MROWS * DIM];

// ---------------------------------------------------------------------------
// Convert X -> hi/lo bf16
// ---------------------------------------------------------------------------
__global__ __launch_bounds__(256) void xconv_kernel(const float* __restrict__ X)
{
    size_t i = ((size_t)blockIdx.x * 256 + threadIdx.x) * 4;
    float4 v = *(const float4*)(X + i);
    float f[4] = {v.x, v.y, v.z, v.w};
    unsigned short h[4], l[4];
    #pragma unroll
    for (int j = 0; j < 4; j++) {
        __nv_bfloat16 hb = __float2bfloat16_rn(f[j]);
        h[j] = __bfloat16_as_ushort(hb);
        l[j] = __bfloat16_as_ushort(__float2bfloat16_rn(f[j] - __bfloat162float(hb)));
    }
    uint2 hv = make_uint2((unsigned)h[0] | ((unsigned)h[1] << 16),
                          (unsigned)h[2] | ((unsigned)h[3] << 16));
    uint2 lv = make_uint2((unsigned)l[0] | ((unsigned)l[1] << 16),
                          (unsigned)l[2] | ((unsigned)l[3] << 16));
    *(uint2*)(g_xh + i) = hv;
    *(uint2*)(g_xl + i) = lv;
}

// ---------------------------------------------------------------------------
// Transpose + convert W [1024][3072] -> W^T hi/lo bf16 [3072][1024]
// ---------------------------------------------------------------------------
__global__ __launch_bounds__(256) void wconv_kernel(const float* __restrict__ W)
{
    __shared__ float t[32][33];
    const int n0 = blockIdx.x * 32;
    const int k0 = blockIdx.y * 32;
    const int tx = threadIdx.x & 31;
    const int ty = threadIdx.x >> 5;
    #pragma unroll
    for (int i = 0; i < 4; i++)
        t[ty + 8 * i][tx] = W[(size_t)(k0 + ty + 8 * i) * NCOLS + n0 + tx];
    __syncthreads();
    #pragma unroll
    for (int i = 0; i < 4; i++) {
        float v = t[tx][ty + 8 * i];
        __nv_bfloat16 hb = __float2bfloat16_rn(v);
        unsigned short l = __bfloat16_as_ushort(__float2bfloat16_rn(v - __bfloat162float(hb)));
        size_t o = (size_t)(n0 + ty + 8 * i) * DIM + k0 + tx;
        g_wth[o] = __bfloat16_as_ushort(hb);
        g_wtl[o] = l;
    }
}

// ---------------------------------------------------------------------------
// QKV GEMM via HMMA (3-term bf16 split). Epilogue writes per-head bf16 hi/lo
// Q (scaled), K, V arrays directly -- no fp32 qkv scratch.
// ---------------------------------------------------------------------------
#define ROWB   80
#define TILE_B (128 * ROWB)
#define STG_B  (4 * TILE_B)
#define GEMM_SMEM (2 * STG_B)

__global__ __launch_bounds__(256) void qkv_mma_kernel(const float* __restrict__ bias)
{
    extern __shared__ __align__(128) char smem[];
    const unsigned sb = smem_u32(smem);
    const int tid  = threadIdx.x;
    const int wid  = tid >> 5;
    const int lane = tid & 31;

    const int m0 = blockIdx.y * 128;
    const int n0 = blockIdx.x * 128;
    const int wm = (wid & 1) * 64;
    const int wn = (wid >> 1) * 32;

    float acc[4][4][4];
    #pragma unroll
    for (int i = 0; i < 4; i++)
        #pragma unroll
        for (int j = 0; j < 4; j++)
            #pragma unroll
            for (int r = 0; r < 4; r++) acc[i][j][r] = 0.f;

    auto load_stage = [&](int c, int buf) {
        const unsigned base = sb + buf * STG_B;
        const int k0 = c * 32;
        const unsigned short* srcs[4] = {
            g_xh  + (size_t)m0 * DIM + k0,
            g_xl  + (size_t)m0 * DIM + k0,
            g_wth + (size_t)n0 * DIM + k0,
            g_wtl + (size_t)n0 * DIM + k0 };
        #pragma unroll
        for (int t = 0; t < 4; t++) {
            #pragma unroll
            for (int it = 0; it < 2; it++) {
                int idx = tid + 256 * it;
                int row = idx >> 2;
                int c8  = idx & 3;
                cp16(base + t * TILE_B + row * ROWB + c8 * 16,
                     srcs[t] + (size_t)row * DIM + c8 * 8);
            }
        }
    };

    load_stage(0, 0);
    CP_COMMIT();

    for (int c = 0; c < 32; c++) {
        const int buf = c & 1;
        if (c + 1 < 32) {
            load_stage(c + 1, buf ^ 1);
            CP_COMMIT();
            CP_WAIT(1);
        } else {
            CP_WAIT(0);
        }
        __syncthreads();

        const unsigned sAh = sb + buf * STG_B;
        const unsigned sAl = sAh + TILE_B;
        const unsigned sBh = sAh + 2 * TILE_B;
        const unsigned sBl = sAh + 3 * TILE_B;

        #pragma unroll
        for (int k16 = 0; k16 < 2; k16++) {
            const unsigned a_off = (wm + (lane & 15)) * ROWB + (k16 * 16 + (lane >> 4) * 8) * 2;
            unsigned ah[4][4], al[4][4];
            #pragma unroll
            for (int mt = 0; mt < 4; mt++) {
                ldm_x4(ah[mt], sAh + a_off + mt * 16 * ROWB);
                ldm_x4(al[mt], sAl + a_off + mt * 16 * ROWB);
            }
            const int bmat = lane >> 3;
            const unsigned b_off = (wn + (bmat >> 1) * 8 + (lane & 7)) * ROWB
                                 + (k16 * 16 + (bmat & 1) * 8) * 2;
            unsigned bh[2][4], bl[2][4];
            #pragma unroll
            for (int nt2 = 0; nt2 < 2; nt2++) {
                ldm_x4(bh[nt2], sBh + b_off + nt2 * 16 * ROWB);
                ldm_x4(bl[nt2], sBl + b_off + nt2 * 16 * ROWB);
            }
            #pragma unroll
            for (int mt = 0; mt < 4; mt++) {
                #pragma unroll
                for (int nt = 0; nt < 4; nt++) {
                    const int n2 = nt >> 1, hb = (nt & 1) * 2;
                    mma16816(acc[mt][nt], ah[mt], bh[n2][hb], bh[n2][hb + 1]);
                    mma16816(acc[mt][nt], ah[mt], bl[n2][hb], bl[n2][hb + 1]);
                    mma16816(acc[mt][nt], al[mt], bh[n2][hb], bh[n2][hb + 1]);
                }
            }
        }
        __syncthreads();
    }

    // ---- epilogue: bias (+Q scale), hi/lo split, per-head layout store ----
    #pragma unroll
    for (int mt = 0; mt < 4; mt++) {
        const int row  = m0 + wm + mt * 16 + (lane >> 2);
        const int bidx = row >> 10;
        const int srow = row & 1023;
        #pragma unroll
        for (int nt = 0; nt < 4; nt++) {
            const int col    = n0 + wn + nt * 8 + (lane & 3) * 2;
            const int region = col >> 10;
            const int hidx   = (col >> 6) & 15;
            const int d      = col & 63;
            const float sc = (region == 0) ? QK_SCALE : 1.f;
            const float b0 = bias[col], b1 = bias[col + 1];
            float x0 = (acc[mt][nt][0] + b0) * sc;
            float x1 = (acc[mt][nt][1] + b1) * sc;
            float y0 = (acc[mt][nt][2] + b0) * sc;
            float y1 = (acc[mt][nt][3] + b1) * sc;
            unsigned short* ph = (region == 0) ? g_qh : (region == 1) ? g_kh : g_vh;
            unsigned short* pl = (region == 0) ? g_ql : (region == 1) ? g_kl : g_vl;
            size_t o  = (((size_t)bidx * 16 + hidx) * 1024 + srow) * 64 + d;
            size_t o2 = o + 8 * 64;
            unsigned hx = bfpack(x1, x0);
            unsigned lx = bfpack(x1 - __uint_as_float(hx & 0xffff0000u),
                                 x0 - __uint_as_float(hx << 16));
            unsigned hy = bfpack(y1, y0);
            unsigned ly = bfpack(y1 - __uint_as_float(hy & 0xffff0000u),
                                 y0 - __uint_as_float(hy << 16));
            *(unsigned*)(ph + o)  = hx;
            *(unsigned*)(pl + o)  = lx;
            *(unsigned*)(ph + o2) = hy;
            *(unsigned*)(pl + o2) = ly;
        }
    }
}

// ---------------------------------------------------------------------------
// Tensor-core flash attention. CTA = 128 q-rows x one (b,h); 8 warps x 16 rows.
// K-tiles of 128, double-buffered cp.async. 3-term bf16 split on QK^T and PV.
// ---------------------------------------------------------------------------
#define ARB    144                       /* 64 bf16 + 8 pad = 144 B row */
#define TBA    (128 * ARB)               /* 18432 B tile */
#define KV_OFF (2 * TBA)                 /* after Qh, Ql */
#define KVBUF  (4 * TBA)                 /* Kh Kl Vh Vl */
#define MASK_OFF (KV_OFF + 2 * KVBUF)    /* 184320 */
#define ATTN_SMEM (MASK_OFF + 2 * 128 * 4)

__global__ __launch_bounds__(256) void attn_mma_kernel(
    const int* __restrict__ mask, float* __restrict__ out)
{
    extern __shared__ __align__(128) char smem[];
    const unsigned sb = smem_u32(smem);
    float* maskf = (float*)(smem + MASK_OFF);

    const int q0 = blockIdx.x * 128;
    const int bh = blockIdx.y;
    const int b  = bh >> 4;
    const int h  = bh & 15;

    const int tid  = threadIdx.x;
    const int wid  = tid >> 5;
    const int lane = tid & 31;
    const int wq0  = wid * 16;

    const size_t hb_base = (size_t)bh * SEQ * HDIM;

    // ---- Q load (once, cp.async): Qh at 0, Ql at TBA ----
    {
        const size_t qoff = hb_base + (size_t)q0 * HDIM;
        #pragma unroll
        for (int t = 0; t < 2; t++) {
            const unsigned short* src = (t ? g_ql : g_qh) + qoff;
            #pragma unroll
            for (int it = 0; it < 4; it++) {
                int idx = tid + 256 * it;
                int row = idx >> 3;
                int c16 = idx & 7;
                cp16(sb + t * TBA + row * ARB + c16 * 16, src + (size_t)row * HDIM + c16 * 8);
            }
        }
    }

    auto load_kv = [&](int kt, int buf) {
        const unsigned base = sb + KV_OFF + buf * KVBUF;
        const size_t o = hb_base + (size_t)kt * 128 * HDIM;
        const unsigned short* srcs[4] = { g_kh + o, g_kl + o, g_vh + o, g_vl + o };
        #pragma unroll
        for (int t = 0; t < 4; t++) {
            #pragma unroll
            for (int it = 0; it < 4; it++) {
                int idx = tid + 256 * it;
                int row = idx >> 3;
                int c16 = idx & 7;
                cp16(base + t * TBA + row * ARB + c16 * 16,
                     srcs[t] + (size_t)row * HDIM + c16 * 8);
            }
        }
        if (tid < 128)
            maskf[buf * 128 + tid] = mask[b * SEQ + kt * 128 + tid] ? 0.f : -1e30f;
    };

    load_kv(0, 0);
    CP_COMMIT();

    float m0r = -INFINITY, m1r = -INFINITY, l0r = 0.f, l1r = 0.f;
    float accO[8][4];
    #pragma unroll
    for (int i = 0; i < 8; i++)
        #pragma unroll
        for (int j = 0; j < 4; j++) accO[i][j] = 0.f;

    for (int kt = 0; kt < 8; kt++) {
        const int buf = kt & 1;
        if (kt + 1 < 8) {
            load_kv(kt + 1, buf ^ 1);
            CP_COMMIT();
            CP_WAIT(1);
        } else {
            CP_WAIT(0);
        }
        __syncthreads();

        const unsigned sKh = sb + KV_OFF + buf * KVBUF;
        const unsigned sVh = sKh + 2 * TBA;

        // ---- S = Q K^T ----
        float s[16][4];
        #pragma unroll
        for (int i = 0; i < 16; i++)
            #pragma unroll
            for (int j = 0; j < 4; j++) s[i][j] = 0.f;

        const int bmat = lane >> 3;
        #pragma unroll
        for (int k16 = 0; k16 < 4; k16++) {
            const unsigned a_addr = sb + (wq0 + (lane & 15)) * ARB
                                  + (k16 * 16 + (lane >> 4) * 8) * 2;
            unsigned qh[4], ql[4];
            ldm_x4(qh, a_addr);
            ldm_x4(ql, a_addr + TBA);
            #pragma unroll
            for (int g = 0; g < 8; g++) {
                const unsigned b_addr = sKh
                    + (g * 16 + (bmat >> 1) * 8 + (lane & 7)) * ARB
                    + (k16 * 16 + (bmat & 1) * 8) * 2;
                unsigned kh[4], kl[4];
                ldm_x4(kh, b_addr);
                ldm_x4(kl, b_addr + TBA);
                mma16816(s[2*g],   qh, kh[0], kh[1]);
                mma16816(s[2*g],   qh, kl[0], kl[1]);
                mma16816(s[2*g],   ql, kh[0], kh[1]);
                mma16816(s[2*g+1], qh, kh[2], kh[3]);
                mma16816(s[2*g+1], qh, kl[2], kl[3]);
                mma16816(s[2*g+1], ql, kh[2], kh[3]);
            }
        }

        // ---- mask add ----
        const float* madd = maskf + buf * 128;
        #pragma unroll
        for (int t = 0; t < 16; t++) {
            float2 mm = *(const float2*)(madd + t * 8 + (lane & 3) * 2);
            s[t][0] += mm.x; s[t][1] += mm.y;
            s[t][2] += mm.x; s[t][3] += mm.y;
        }

        // ---- online softmax on fragments (rows r=lane>>2 and r+8) ----
        float mx0 = -INFINITY, mx1 = -INFINITY;
        #pragma unroll
        for (int t = 0; t < 16; t++) {
            mx0 = fmaxf(mx0, fmaxf(s[t][0], s[t][1]));
            mx1 = fmaxf(mx1, fmaxf(s[t][2], s[t][3]));
        }
        mx0 = fmaxf(mx0, __shfl_xor_sync(0xffffffffu, mx0, 1));
        mx0 = fmaxf(mx0, __shfl_xor_sync(0xffffffffu, mx0, 2));
        mx1 = fmaxf(mx1, __shfl_xor_sync(0xffffffffu, mx1, 1));
        mx1 = fmaxf(mx1, __shfl_xor_sync(0xffffffffu, mx1, 2));

        const float mn0 = fmaxf(m0r, mx0);
        const float mn1 = fmaxf(m1r, mx1);
        const float a0 = __expf(m0r - mn0);
        const float a1 = __expf(m1r - mn1);
        m0r = mn0; m1r = mn1;

        float ls0 = 0.f, ls1 = 0.f;
        #pragma unroll
        for (int t = 0; t < 16; t++) {
            s[t][0] = __expf(s[t][0] - mn0);
            s[t][1] = __expf(s[t][1] - mn0);
            s[t][2] = __expf(s[t][2] - mn1);
            s[t][3] = __expf(s[t][3] - mn1);
            ls0 += s[t][0] + s[t][1];
            ls1 += s[t][2] + s[t][3];
        }
        ls0 += __shfl_xor_sync(0xffffffffu, ls0, 1);
        ls0 += __shfl_xor_sync(0xffffffffu, ls0, 2);
        ls1 += __shfl_xor_sync(0xffffffffu, ls1, 1);
        ls1 += __shfl_xor_sync(0xffffffffu, ls1, 2);
        l0r = l0r * a0 + ls0;
        l1r = l1r * a1 + ls1;

        #pragma unroll
        for (int nt = 0; nt < 8; nt++) {
            accO[nt][0] *= a0; accO[nt][1] *= a0;
            accO[nt][2] *= a1; accO[nt][3] *= a1;
        }

        // ---- O += P V  (P split to bf16 hi/lo in registers) ----
        #pragma unroll
        for (int k16 = 0; k16 < 8; k16++) {
            unsigned ph[4], pl[4];
            #pragma unroll
            for (int half = 0; half < 2; half++) {
                const float* sp = s[2 * k16 + half];
                unsigned h01 = bfpack(sp[1], sp[0]);
                unsigned l01 = bfpack(sp[1] - __uint_as_float(h01 & 0xffff0000u),
                                      sp[0] - __uint_as_float(h01 << 16));
                unsigned h23 = bfpack(sp[3], sp[2]);
                unsigned l23 = bfpack(sp[3] - __uint_as_float(h23 & 0xffff0000u),
                                      sp[2] - __uint_as_float(h23 << 16));
                ph[2 * half] = h01; ph[2 * half + 1] = h23;
                pl[2 * half] = l01; pl[2 * half + 1] = l23;
            }
            #pragma unroll
            for (int dg = 0; dg < 4; dg++) {
                const unsigned v_addr = sVh + (k16 * 16 + (lane & 15)) * ARB
                                      + (dg * 16 + (lane >> 4) * 8) * 2;
                unsigned vh[4], vl[4];
                ldm_x4t(vh, v_addr);
                ldm_x4t(vl, v_addr + TBA);
                mma16816(accO[2*dg],   ph, vh[0], vh[1]);
                mma16816(accO[2*dg],   ph, vl[0], vl[1]);
                mma16816(accO[2*dg],   pl, vh[0], vh[1]);
                mma16816(accO[2*dg+1], ph, vh[2], vh[3]);
                mma16816(accO[2*dg+1], ph, vl[2], vl[3]);
                mma16816(accO[2*dg+1], pl, vh[2], vh[3]);
            }
        }
        __syncthreads();
    }

    // ---- epilogue: normalize, store ----
    const float inv0 = 1.f / l0r;
    const float inv1 = 1.f / l1r;
    const int row = q0 + wq0 + (lane >> 2);
    float* orow0 = out + (size_t)(b * SEQ + row) * DIM + h * HDIM;
    float* orow1 = orow0 + 8 * DIM;
    #pragma unroll
    for (int nt = 0; nt < 8; nt++) {
        const int d = nt * 8 + (lane & 3) * 2;
        *(float2*)(orow0 + d) = make_float2(accO[nt][0] * inv0, accO[nt][1] * inv0);
        *(float2*)(orow1 + d) = make_float2(accO[nt][2] * inv1, accO[nt][3] * inv1);
    }
}

// ---------------------------------------------------------------------------
extern "C" void kernel_launch(void* const* d_in, const int* in_sizes, int n_in,
                              void* d_out, int out_size)
{
    const float* x    = (const float*)d_in[0];   // [4,1024,1024]
    const int*   mask = (const int*)  d_in[1];   // [4,1024]
    const float* W    = (const float*)d_in[2];   // [1024,3072]
    const float* bias = (const float*)d_in[3];   // [3072]
    float* out = (float*)d_out;                  // [4,1024,1024]

    cudaFuncSetAttribute(qkv_mma_kernel,
                         cudaFuncAttributeMaxDynamicSharedMemorySize, GEMM_SMEM);
    cudaFuncSetAttribute(attn_mma_kernel,
                         cudaFuncAttributeMaxDynamicSharedMemorySize, ATTN_SMEM);

    xconv_kernel<<<(MROWS * DIM) / (256 * 4), 256>>>(x);
    wconv_kernel<<<dim3(NCOLS / 32, DIM / 32), 256>>>(W);

    dim3 gg(NCOLS / 128, MROWS / 128);           // (24, 32)
    qkv_mma_kernel<<<gg, 256, GEMM_SMEM>>>(bias);

    dim3 ga(SEQ / 128, BATCH * NH);              // (8, 64)
    attn_mma_kernel<<<ga, 256, ATTN_SMEM>>>(mask, out);
}

// round 12
// speedup vs baseline: 4.1819x; 1.1233x over previous
#include <cuda_runtime.h>
#include <cuda_bf16.h>
#include <math.h>

#define BATCH 4
#define SEQ   1024
#define DIM   1024
#define NH    16
#define HDIM  64
#define MROWS (BATCH*SEQ)   /* 4096 */
#define NCOLS (3*DIM)       /* 3072 */
#define QK_SCALE 0.125f     /* 1/sqrt(64) */

typedef unsigned long long ull;

// ---------------- warp-MMA helpers (baseline sm_80 features only) ----------------
__device__ __forceinline__ unsigned smem_u32(const void* p) {
    unsigned a;
    asm("{ .reg .u64 t; cvta.to.shared.u64 t, %1; cvt.u32.u64 %0, t; }" : "=r"(a) : "l"(p));
    return a;
}
__device__ __forceinline__ void ldm_x4(unsigned* r, unsigned addr) {
    asm volatile("ldmatrix.sync.aligned.m8n8.x4.shared.b16 {%0,%1,%2,%3}, [%4];"
        : "=r"(r[0]), "=r"(r[1]), "=r"(r[2]), "=r"(r[3]) : "r"(addr));
}
__device__ __forceinline__ void ldm_x4t(unsigned* r, unsigned addr) {
    asm volatile("ldmatrix.sync.aligned.m8n8.x4.trans.shared.b16 {%0,%1,%2,%3}, [%4];"
        : "=r"(r[0]), "=r"(r[1]), "=r"(r[2]), "=r"(r[3]) : "r"(addr));
}
__device__ __forceinline__ void mma16816(float* c, const unsigned* a, unsigned b0, unsigned b1) {
    asm volatile("mma.sync.aligned.m16n8k16.row.col.f32.bf16.bf16.f32 "
        "{%0,%1,%2,%3}, {%4,%5,%6,%7}, {%8,%9}, {%0,%1,%2,%3};"
        : "+f"(c[0]), "+f"(c[1]), "+f"(c[2]), "+f"(c[3])
        : "r"(a[0]), "r"(a[1]), "r"(a[2]), "r"(a[3]), "r"(b0), "r"(b1));
}
__device__ __forceinline__ void cp16(unsigned dst, const void* src) {
    asm volatile("cp.async.cg.shared.global [%0], [%1], 16;" :: "r"(dst), "l"(src));
}
#define CP_COMMIT() asm volatile("cp.async.commit_group;" ::: "memory")
#define CP_WAIT(n)  asm volatile("cp.async.wait_group %0;" :: "n"(n) : "memory")

// pack two f32 -> bf16x2 (hi -> upper half, lo -> lower half)
__device__ __forceinline__ unsigned bfpack(float hi, float lo) {
    unsigned r; asm("cvt.rn.bf16x2.f32 %0, %1, %2;" : "=r"(r) : "f"(hi), "f"(lo)); return r;
}

// ---------------- global scratch ----------------
__device__ unsigned short g_xh[(size_t)MROWS * DIM];     // X hi bf16
__device__ unsigned short g_xl[(size_t)MROWS * DIM];     // X lo bf16
__device__ unsigned short g_wth[(size_t)NCOLS * DIM];    // W^T hi [N][K]
__device__ unsigned short g_wtl[(size_t)NCOLS * DIM];    // W^T lo
// per-head layout [(b*16+h)*1024 + s][d], bf16 hi/lo. Q pre-scaled.
__device__ unsigned short g_qh[(size_t)MROWS * DIM];
__device__ unsigned short g_ql[(size_t)MROWS * DIM];
__device__ unsigned short g_kh[(size_t)MROWS * DIM];
__device__ unsigned short g_kl[(size_t)MROWS * DIM];
__device__ unsigned short g_vh[(size_t)MROWS * DIM];
__device__ unsigned short g_vl[(size_t)MROWS * DIM];

// ---------------------------------------------------------------------------
// Convert X -> hi/lo bf16
// ---------------------------------------------------------------------------
__global__ __launch_bounds__(256) void xconv_kernel(const float* __restrict__ X)
{
    size_t i = ((size_t)blockIdx.x * 256 + threadIdx.x) * 4;
    float4 v = *(const float4*)(X + i);
    float f[4] = {v.x, v.y, v.z, v.w};
    unsigned short h[4], l[4];
    #pragma unroll
    for (int j = 0; j < 4; j++) {
        __nv_bfloat16 hb = __float2bfloat16_rn(f[j]);
        h[j] = __bfloat16_as_ushort(hb);
        l[j] = __bfloat16_as_ushort(__float2bfloat16_rn(f[j] - __bfloat162float(hb)));
    }
    uint2 hv = make_uint2((unsigned)h[0] | ((unsigned)h[1] << 16),
                          (unsigned)h[2] | ((unsigned)h[3] << 16));
    uint2 lv = make_uint2((unsigned)l[0] | ((unsigned)l[1] << 16),
                          (unsigned)l[2] | ((unsigned)l[3] << 16));
    *(uint2*)(g_xh + i) = hv;
    *(uint2*)(g_xl + i) = lv;
}

// ---------------------------------------------------------------------------
// Transpose + convert W [1024][3072] -> W^T hi/lo bf16 [3072][1024]
// ---------------------------------------------------------------------------
__global__ __launch_bounds__(256) void wconv_kernel(const float* __restrict__ W)
{
    __shared__ float t[32][33];
    const int n0 = blockIdx.x * 32;
    const int k0 = blockIdx.y * 32;
    const int tx = threadIdx.x & 31;
    const int ty = threadIdx.x >> 5;
    #pragma unroll
    for (int i = 0; i < 4; i++)
        t[ty + 8 * i][tx] = W[(size_t)(k0 + ty + 8 * i) * NCOLS + n0 + tx];
    __syncthreads();
    #pragma unroll
    for (int i = 0; i < 4; i++) {
        float v = t[tx][ty + 8 * i];
        __nv_bfloat16 hb = __float2bfloat16_rn(v);
        unsigned short l = __bfloat16_as_ushort(__float2bfloat16_rn(v - __bfloat162float(hb)));
        size_t o = (size_t)(n0 + ty + 8 * i) * DIM + k0 + tx;
        g_wth[o] = __bfloat16_as_ushort(hb);
        g_wtl[o] = l;
    }
}

// ---------------------------------------------------------------------------
// QKV GEMM via HMMA (3-term bf16 split). Epilogue writes per-head bf16 hi/lo
// Q (scaled), K, V arrays directly. launch_bounds(256,2) -> 2 CTAs/SM.
// ---------------------------------------------------------------------------
#define ROWB   80
#define TILE_B (128 * ROWB)
#define STG_B  (4 * TILE_B)
#define GEMM_SMEM (2 * STG_B)

__global__ __launch_bounds__(256, 2) void qkv_mma_kernel(const float* __restrict__ bias)
{
    extern __shared__ __align__(128) char smem[];
    const unsigned sb = smem_u32(smem);
    const int tid  = threadIdx.x;
    const int wid  = tid >> 5;
    const int lane = tid & 31;

    const int m0 = blockIdx.y * 128;
    const int n0 = blockIdx.x * 128;
    const int wm = (wid & 1) * 64;
    const int wn = (wid >> 1) * 32;

    float acc[4][4][4];
    #pragma unroll
    for (int i = 0; i < 4; i++)
        #pragma unroll
        for (int j = 0; j < 4; j++)
            #pragma unroll
            for (int r = 0; r < 4; r++) acc[i][j][r] = 0.f;

    auto load_stage = [&](int c, int buf) {
        const unsigned base = sb + buf * STG_B;
        const int k0 = c * 32;
        const unsigned short* srcs[4] = {
            g_xh  + (size_t)m0 * DIM + k0,
            g_xl  + (size_t)m0 * DIM + k0,
            g_wth + (size_t)n0 * DIM + k0,
            g_wtl + (size_t)n0 * DIM + k0 };
        #pragma unroll
        for (int t = 0; t < 4; t++) {
            #pragma unroll
            for (int it = 0; it < 2; it++) {
                int idx = tid + 256 * it;
                int row = idx >> 2;
                int c8  = idx & 3;
                cp16(base + t * TILE_B + row * ROWB + c8 * 16,
                     srcs[t] + (size_t)row * DIM + c8 * 8);
            }
        }
    };

    load_stage(0, 0);
    CP_COMMIT();

    for (int c = 0; c < 32; c++) {
        const int buf = c & 1;
        if (c + 1 < 32) {
            load_stage(c + 1, buf ^ 1);
            CP_COMMIT();
            CP_WAIT(1);
        } else {
            CP_WAIT(0);
        }
        __syncthreads();

        const unsigned sAh = sb + buf * STG_B;
        const unsigned sAl = sAh + TILE_B;
        const unsigned sBh = sAh + 2 * TILE_B;
        const unsigned sBl = sAh + 3 * TILE_B;

        #pragma unroll
        for (int k16 = 0; k16 < 2; k16++) {
            // B fragments first (held), A streamed per mt -> smaller live set
            const int bmat = lane >> 3;
            const unsigned b_off = (wn + (bmat >> 1) * 8 + (lane & 7)) * ROWB
                                 + (k16 * 16 + (bmat & 1) * 8) * 2;
            unsigned bh[2][4], bl[2][4];
            #pragma unroll
            for (int nt2 = 0; nt2 < 2; nt2++) {
                ldm_x4(bh[nt2], sBh + b_off + nt2 * 16 * ROWB);
                ldm_x4(bl[nt2], sBl + b_off + nt2 * 16 * ROWB);
            }
            const unsigned a_off = (wm + (lane & 15)) * ROWB + (k16 * 16 + (lane >> 4) * 8) * 2;
            #pragma unroll
            for (int mt = 0; mt < 4; mt++) {
                unsigned ah[4], al[4];
                ldm_x4(ah, sAh + a_off + mt * 16 * ROWB);
                ldm_x4(al, sAl + a_off + mt * 16 * ROWB);
                #pragma unroll
                for (int nt = 0; nt < 4; nt++) {
                    const int n2 = nt >> 1, hb = (nt & 1) * 2;
                    mma16816(acc[mt][nt], ah, bh[n2][hb], bh[n2][hb + 1]);
                    mma16816(acc[mt][nt], ah, bl[n2][hb], bl[n2][hb + 1]);
                    mma16816(acc[mt][nt], al, bh[n2][hb], bh[n2][hb + 1]);
                }
            }
        }
        __syncthreads();
    }

    // ---- epilogue: bias (+Q scale), hi/lo split, per-head layout store ----
    #pragma unroll
    for (int mt = 0; mt < 4; mt++) {
        const int row  = m0 + wm + mt * 16 + (lane >> 2);
        const int bidx = row >> 10;
        const int srow = row & 1023;
        #pragma unroll
        for (int nt = 0; nt < 4; nt++) {
            const int col    = n0 + wn + nt * 8 + (lane & 3) * 2;
            const int region = col >> 10;
            const int hidx   = (col >> 6) & 15;
            const int d      = col & 63;
            const float sc = (region == 0) ? QK_SCALE : 1.f;
            const float b0 = bias[col], b1 = bias[col + 1];
            float x0 = (acc[mt][nt][0] + b0) * sc;
            float x1 = (acc[mt][nt][1] + b1) * sc;
            float y0 = (acc[mt][nt][2] + b0) * sc;
            float y1 = (acc[mt][nt][3] + b1) * sc;
            unsigned short* ph = (region == 0) ? g_qh : (region == 1) ? g_kh : g_vh;
            unsigned short* pl = (region == 0) ? g_ql : (region == 1) ? g_kl : g_vl;
            size_t o  = (((size_t)bidx * 16 + hidx) * 1024 + srow) * 64 + d;
            size_t o2 = o + 8 * 64;
            unsigned hx = bfpack(x1, x0);
            unsigned lx = bfpack(x1 - __uint_as_float(hx & 0xffff0000u),
                                 x0 - __uint_as_float(hx << 16));
            unsigned hy = bfpack(y1, y0);
            unsigned ly = bfpack(y1 - __uint_as_float(hy & 0xffff0000u),
                                 y0 - __uint_as_float(hy << 16));
            *(unsigned*)(ph + o)  = hx;
            *(unsigned*)(pl + o)  = lx;
            *(unsigned*)(ph + o2) = hy;
            *(unsigned*)(pl + o2) = ly;
        }
    }
}

// ---------------------------------------------------------------------------
// Tensor-core flash attention. CTA = 128 q-rows x one (b,h); 8 warps x 16 rows.
// KV-tiles of 64 (smem 111KB -> 2 CTAs/SM), double-buffered cp.async.
// 3-term bf16 split on QK^T and PV.
// ---------------------------------------------------------------------------
#define ARB    144                       /* 64 bf16 + 8 pad = 144 B row */
#define TBA    (128 * ARB)               /* Q tile: 18432 B */
#define TBK    (64 * ARB)                /* KV tile: 9216 B */
#define KV_OFF (2 * TBA)                 /* after Qh, Ql */
#define KVBUF  (4 * TBK)                 /* Kh Kl Vh Vl = 36864 */
#define MASK_OFF (KV_OFF + 2 * KVBUF)    /* 110592 */
#define ATTN_SMEM (MASK_OFF + 2 * 64 * 4) /* 111104 */

__global__ __launch_bounds__(256, 2) void attn_mma_kernel(
    const int* __restrict__ mask, float* __restrict__ out)
{
    extern __shared__ __align__(128) char smem[];
    const unsigned sb = smem_u32(smem);
    float* maskf = (float*)(smem + MASK_OFF);

    const int q0 = blockIdx.x * 128;
    const int bh = blockIdx.y;
    const int b  = bh >> 4;
    const int h  = bh & 15;

    const int tid  = threadIdx.x;
    const int wid  = tid >> 5;
    const int lane = tid & 31;
    const int wq0  = wid * 16;

    const size_t hb_base = (size_t)bh * SEQ * HDIM;

    // ---- Q load (once, cp.async): Qh at 0, Ql at TBA ----
    {
        const size_t qoff = hb_base + (size_t)q0 * HDIM;
        #pragma unroll
        for (int t = 0; t < 2; t++) {
            const unsigned short* src = (t ? g_ql : g_qh) + qoff;
            #pragma unroll
            for (int it = 0; it < 4; it++) {
                int idx = tid + 256 * it;
                int row = idx >> 3;
                int c16 = idx & 7;
                cp16(sb + t * TBA + row * ARB + c16 * 16, src + (size_t)row * HDIM + c16 * 8);
            }
        }
    }

    auto load_kv = [&](int kt, int buf) {
        const unsigned base = sb + KV_OFF + buf * KVBUF;
        const size_t o = hb_base + (size_t)kt * 64 * HDIM;
        const unsigned short* srcs[4] = { g_kh + o, g_kl + o, g_vh + o, g_vl + o };
        #pragma unroll
        for (int t = 0; t < 4; t++) {
            #pragma unroll
            for (int it = 0; it < 2; it++) {
                int idx = tid + 256 * it;       // 0..511
                int row = idx >> 3;             // 0..63
                int c16 = idx & 7;
                cp16(base + t * TBK + row * ARB + c16 * 16,
                     srcs[t] + (size_t)row * HDIM + c16 * 8);
            }
        }
        if (tid < 64)
            maskf[buf * 64 + tid] = mask[b * SEQ + kt * 64 + tid] ? 0.f : -1e30f;
    };

    load_kv(0, 0);
    CP_COMMIT();

    float m0r = -INFINITY, m1r = -INFINITY, l0r = 0.f, l1r = 0.f;
    float accO[8][4];
    #pragma unroll
    for (int i = 0; i < 8; i++)
        #pragma unroll
        for (int j = 0; j < 4; j++) accO[i][j] = 0.f;

    for (int kt = 0; kt < 16; kt++) {
        const int buf = kt & 1;
        if (kt + 1 < 16) {
            load_kv(kt + 1, buf ^ 1);
            CP_COMMIT();
            CP_WAIT(1);
        } else {
            CP_WAIT(0);
        }
        __syncthreads();

        const unsigned sKh = sb + KV_OFF + buf * KVBUF;
        const unsigned sVh = sKh + 2 * TBK;

        // ---- S = Q K^T ----
        float s[8][4];
        #pragma unroll
        for (int i = 0; i < 8; i++)
            #pragma unroll
            for (int j = 0; j < 4; j++) s[i][j] = 0.f;

        const int bmat = lane >> 3;
        #pragma unroll
        for (int k16 = 0; k16 < 4; k16++) {
            const unsigned a_addr = sb + (wq0 + (lane & 15)) * ARB
                                  + (k16 * 16 + (lane >> 4) * 8) * 2;
            unsigned qh[4], ql[4];
            ldm_x4(qh, a_addr);
            ldm_x4(ql, a_addr + TBA);
            #pragma unroll
            for (int g = 0; g < 4; g++) {
                const unsigned b_addr = sKh
                    + (g * 16 + (bmat >> 1) * 8 + (lane & 7)) * ARB
                    + (k16 * 16 + (bmat & 1) * 8) * 2;
                unsigned kh[4], kl[4];
                ldm_x4(kh, b_addr);
                ldm_x4(kl, b_addr + TBK);
                mma16816(s[2*g],   qh, kh[0], kh[1]);
                mma16816(s[2*g],   qh, kl[0], kl[1]);
                mma16816(s[2*g],   ql, kh[0], kh[1]);
                mma16816(s[2*g+1], qh, kh[2], kh[3]);
                mma16816(s[2*g+1], qh, kl[2], kl[3]);
                mma16816(s[2*g+1], ql, kh[2], kh[3]);
            }
        }

        // ---- mask add ----
        const float* madd = maskf + buf * 64;
        #pragma unroll
        for (int t = 0; t < 8; t++) {
            float2 mm = *(const float2*)(madd + t * 8 + (lane & 3) * 2);
            s[t][0] += mm.x; s[t][1] += mm.y;
            s[t][2] += mm.x; s[t][3] += mm.y;
        }

        // ---- online softmax on fragments (rows r=lane>>2 and r+8) ----
        float mx0 = -INFINITY, mx1 = -INFINITY;
        #pragma unroll
        for (int t = 0; t < 8; t++) {
            mx0 = fmaxf(mx0, fmaxf(s[t][0], s[t][1]));
            mx1 = fmaxf(mx1, fmaxf(s[t][2], s[t][3]));
        }
        mx0 = fmaxf(mx0, __shfl_xor_sync(0xffffffffu, mx0, 1));
        mx0 = fmaxf(mx0, __shfl_xor_sync(0xffffffffu, mx0, 2));
        mx1 = fmaxf(mx1, __shfl_xor_sync(0xffffffffu, mx1, 1));
        mx1 = fmaxf(mx1, __shfl_xor_sync(0xffffffffu, mx1, 2));

        const float mn0 = fmaxf(m0r, mx0);
        const float mn1 = fmaxf(m1r, mx1);
        const float a0 = __expf(m0r - mn0);
        const float a1 = __expf(m1r - mn1);
        m0r = mn0; m1r = mn1;

        float ls0 = 0.f, ls1 = 0.f;
        #pragma unroll
        for (int t = 0; t < 8; t++) {
            s[t][0] = __expf(s[t][0] - mn0);
            s[t][1] = __expf(s[t][1] - mn0);
            s[t][2] = __expf(s[t][2] - mn1);
            s[t][3] = __expf(s[t][3] - mn1);
            ls0 += s[t][0] + s[t][1];
            ls1 += s[t][2] + s[t][3];
        }
        ls0 += __shfl_xor_sync(0xffffffffu, ls0, 1);
        ls0 += __shfl_xor_sync(0xffffffffu, ls0, 2);
        ls1 += __shfl_xor_sync(0xffffffffu, ls1, 1);
        ls1 += __shfl_xor_sync(0xffffffffu, ls1, 2);
        l0r = l0r * a0 + ls0;
        l1r = l1r * a1 + ls1;

        #pragma unroll
        for (int nt = 0; nt < 8; nt++) {
            accO[nt][0] *= a0; accO[nt][1] *= a0;
            accO[nt][2] *= a1; accO[nt][3] *= a1;
        }

        // ---- O += P V  (P split to bf16 hi/lo in registers) ----
        #pragma unroll
        for (int k16 = 0; k16 < 4; k16++) {
            unsigned ph[4], pl[4];
            #pragma unroll
            for (int half = 0; half < 2; half++) {
                const float* sp = s[2 * k16 + half];
                unsigned h01 = bfpack(sp[1], sp[0]);
                unsigned l01 = bfpack(sp[1] - __uint_as_float(h01 & 0xffff0000u),
                                      sp[0] - __uint_as_float(h01 << 16));
                unsigned h23 = bfpack(sp[3], sp[2]);
                unsigned l23 = bfpack(sp[3] - __uint_as_float(h23 & 0xffff0000u),
                                      sp[2] - __uint_as_float(h23 << 16));
                ph[2 * half] = h01; ph[2 * half + 1] = h23;
                pl[2 * half] = l01; pl[2 * half + 1] = l23;
            }
            #pragma unroll
            for (int dg = 0; dg < 4; dg++) {
                const unsigned v_addr = sVh + (k16 * 16 + (lane & 15)) * ARB
                                      + (dg * 16 + (lane >> 4) * 8) * 2;
                unsigned vh[4], vl[4];
                ldm_x4t(vh, v_addr);
                ldm_x4t(vl, v_addr + TBK);
                mma16816(accO[2*dg],   ph, vh[0], vh[1]);
                mma16816(accO[2*dg],   ph, vl[0], vl[1]);
                mma16816(accO[2*dg],   pl, vh[0], vh[1]);
                mma16816(accO[2*dg+1], ph, vh[2], vh[3]);
                mma16816(accO[2*dg+1], ph, vl[2], vl[3]);
                mma16816(accO[2*dg+1], pl, vh[2], vh[3]);
            }
        }
        __syncthreads();
    }

    // ---- epilogue: normalize, store ----
    const float inv0 = 1.f / l0r;
    const float inv1 = 1.f / l1r;
    const int row = q0 + wq0 + (lane >> 2);
    float* orow0 = out + (size_t)(b * SEQ + row) * DIM + h * HDIM;
    float* orow1 = orow0 + 8 * DIM;
    #pragma unroll
    for (int nt = 0; nt < 8; nt++) {
        const int d = nt * 8 + (lane & 3) * 2;
        *(float2*)(orow0 + d) = make_float2(accO[nt][0] * inv0, accO[nt][1] * inv0);
        *(float2*)(orow1 + d) = make_float2(accO[nt][2] * inv1, accO[nt][3] * inv1);
    }
}

// ---------------------------------------------------------------------------
extern "C" void kernel_launch(void* const* d_in, const int* in_sizes, int n_in,
                              void* d_out, int out_size)
{
    const float* x    = (const float*)d_in[0];   // [4,1024,1024]
    const int*   mask = (const int*)  d_in[1];   // [4,1024]
    const float* W    = (const float*)d_in[2];   // [1024,3072]
    const float* bias = (const float*)d_in[3];   // [3072]
    float* out = (float*)d_out;                  // [4,1024,1024]

    cudaFuncSetAttribute(qkv_mma_kernel,
                         cudaFuncAttributeMaxDynamicSharedMemorySize, GEMM_SMEM);
    cudaFuncSetAttribute(attn_mma_kernel,
                         cudaFuncAttributeMaxDynamicSharedMemorySize, ATTN_SMEM);

    xconv_kernel<<<(MROWS * DIM) / (256 * 4), 256>>>(x);
    wconv_kernel<<<dim3(NCOLS / 32, DIM / 32), 256>>>(W);

    dim3 gg(NCOLS / 128, MROWS / 128);           // (24, 32)
    qkv_mma_kernel<<<gg, 256, GEMM_SMEM>>>(bias);

    dim3 ga(SEQ / 128, BATCH * NH);              // (8, 64)
    attn_mma_kernel<<<ga, 256, ATTN_SMEM>>>(mask, out);
}